// round 3
// baseline (speedup 1.0000x reference)
#include <cuda_runtime.h>
#include <math.h>

#define BB 8
#define NN 2048
#define CC 128
#define DD 64
#define NH 1024
#define BM 64
#define KT 32

// Scratch (device globals: no allocation allowed)
__device__ float g_H[BB * NN * DD];   // hidden [B,N,D]
__device__ float g_s1[BB * NN];
__device__ float g_s2[BB * NN];
__device__ float g_e[BB * NN];        // exp(t - max) per batch, period-1024 duplicated

// ---------------------------------------------------------------------------
// Kernel 1: H = x @ W  and s1 = H.a1, s2 = H.a2
// 256 threads = 4 rows x 64 cols
// ---------------------------------------------------------------------------
__global__ __launch_bounds__(256) void k_hidden(const float* __restrict__ x,
                                                const float* __restrict__ Wm,
                                                const float* __restrict__ av) {
    __shared__ float xs[4][CC];
    __shared__ float part1[8], part2[8];
    int tid = threadIdx.x;
    int lr  = tid >> 6;       // local row 0..3
    int d   = tid & 63;
    int base = blockIdx.x * 4;

    for (int q = tid; q < 4 * CC; q += 256) {
        xs[q >> 7][q & 127] = x[base * CC + q];
    }
    __syncthreads();

    float acc = 0.f;
#pragma unroll
    for (int k = 0; k < CC; k++) acc = fmaf(xs[lr][k], Wm[k * DD + d], acc);

    int row = base + lr;      // global row in [0, B*N)
    g_H[row * DD + d] = acc;

    float p1 = acc * av[d];
    float p2 = acc * av[DD + d];
#pragma unroll
    for (int o = 16; o > 0; o >>= 1) {
        p1 += __shfl_down_sync(0xffffffffu, p1, o);
        p2 += __shfl_down_sync(0xffffffffu, p2, o);
    }
    int w = tid >> 5;
    if ((tid & 31) == 0) { part1[w] = p1; part2[w] = p2; }
    __syncthreads();
    if (d == 0) {
        g_s1[row] = part1[2 * lr] + part1[2 * lr + 1];
        g_s2[row] = part2[2 * lr] + part2[2 * lr + 1];
    }
}

// ---------------------------------------------------------------------------
// Kernel 2: per batch, t[j] = lrelu(s1[2j] + s2[2j+1]) for j<1024 (period 1024),
// e[j] = exp(t - max). One block per batch.
// ---------------------------------------------------------------------------
__global__ __launch_bounds__(256) void k_prep() {
    int b = blockIdx.x;
    __shared__ float ts[NH];
    __shared__ float red[256];
    const float* s1 = g_s1 + b * NN;
    const float* s2 = g_s2 + b * NN;
    int tid = threadIdx.x;

    float mx = -1e30f;
    for (int j = tid; j < NH; j += 256) {
        float v = s1[2 * j] + s2[2 * j + 1];
        v = v > 0.f ? v : 0.2f * v;
        ts[j] = v;
        mx = fmaxf(mx, v);
    }
    red[tid] = mx;
    __syncthreads();
    for (int o = 128; o > 0; o >>= 1) {
        if (tid < o) red[tid] = fmaxf(red[tid], red[tid + o]);
        __syncthreads();
    }
    mx = red[0];
    for (int j = tid; j < NH; j += 256) {
        float e = expf(ts[j] - mx);
        g_e[b * NN + j] = e;
        g_e[b * NN + NH + j] = e;
    }
}

// ---------------------------------------------------------------------------
// Kernel 3: fused attention GEMM + epilogue.
// grid (32 row-blocks, 8 batches), 256 threads. Tile: 64 rows x 64 cols, K=32.
// accA accumulates j in [0,1024), accB accumulates j in [1024,2048).
// Per-row aux (counts for lower rows, e-weighted denominator for upper rows)
// computed from the adj smem tile by threads 0..63.
// ---------------------------------------------------------------------------
#define GEMM_KK(ACC)                                                          \
    _Pragma("unroll")                                                         \
    for (int kk = 0; kk < KT; kk++) {                                         \
        float4 bf = *(const float4*)&Hs[kk][tx4];                             \
        float a0 = As[ty4 + 0][kk];                                           \
        float a1 = As[ty4 + 1][kk];                                           \
        float a2 = As[ty4 + 2][kk];                                           \
        float a3 = As[ty4 + 3][kk];                                           \
        ACC[0][0] = fmaf(a0, bf.x, ACC[0][0]);                                \
        ACC[0][1] = fmaf(a0, bf.y, ACC[0][1]);                                \
        ACC[0][2] = fmaf(a0, bf.z, ACC[0][2]);                                \
        ACC[0][3] = fmaf(a0, bf.w, ACC[0][3]);                                \
        ACC[1][0] = fmaf(a1, bf.x, ACC[1][0]);                                \
        ACC[1][1] = fmaf(a1, bf.y, ACC[1][1]);                                \
        ACC[1][2] = fmaf(a1, bf.z, ACC[1][2]);                                \
        ACC[1][3] = fmaf(a1, bf.w, ACC[1][3]);                                \
        ACC[2][0] = fmaf(a2, bf.x, ACC[2][0]);                                \
        ACC[2][1] = fmaf(a2, bf.y, ACC[2][1]);                                \
        ACC[2][2] = fmaf(a2, bf.z, ACC[2][2]);                                \
        ACC[2][3] = fmaf(a2, bf.w, ACC[2][3]);                                \
        ACC[3][0] = fmaf(a3, bf.x, ACC[3][0]);                                \
        ACC[3][1] = fmaf(a3, bf.y, ACC[3][1]);                                \
        ACC[3][2] = fmaf(a3, bf.z, ACC[3][2]);                                \
        ACC[3][3] = fmaf(a3, bf.w, ACC[3][3]);                                \
    }

#define TILE_ITER(ACC, AUX)                                                   \
    {                                                                         \
        int j0 = kt * KT;                                                     \
        __syncthreads();                                                      \
        _Pragma("unroll")                                                     \
        for (int q = 0; q < (BM * KT) / 256; q++) {                           \
            int e  = tid + q * 256;                                           \
            int ii = e >> 5;                                                  \
            int kk = e & 31;                                                  \
            int v  = adj[(i0 + ii) * NN + j0 + kk];                           \
            As[ii][kk] = (v > 0) ? 1.0f : 0.0f;                               \
        }                                                                     \
        _Pragma("unroll")                                                     \
        for (int q = 0; q < (KT * DD) / 256; q++) {                           \
            int e  = tid + q * 256;                                           \
            int kk = e >> 6;                                                  \
            int dd = e & 63;                                                  \
            float ew = lower ? 1.0f : eb[j0 + kk];                            \
            Hs[kk][dd] = Hb[(j0 + kk) * DD + dd] * ew;                        \
        }                                                                     \
        __syncthreads();                                                      \
        GEMM_KK(ACC)                                                          \
        if (tid < BM) {                                                       \
            float s = 0.f;                                                    \
            _Pragma("unroll")                                                 \
            for (int kk = 0; kk < KT; kk++) {                                 \
                float ew = lower ? 1.0f : eb[j0 + kk];                        \
                s = fmaf(As[tid][kk], ew, s);                                 \
            }                                                                 \
            AUX += s;                                                         \
        }                                                                     \
    }

__global__ __launch_bounds__(256) void k_main(const int* __restrict__ adj,
                                              const float* __restrict__ bias,
                                              float* __restrict__ out) {
    __shared__ float As[BM][KT + 1];
    __shared__ float Hs[KT][DD];
    __shared__ float auxS[2][BM];

    int tid = threadIdx.x;
    int tx  = tid & 15;
    int ty  = tid >> 4;
    int tx4 = tx * 4;
    int ty4 = ty * 4;
    int rb  = blockIdx.x;
    int b   = blockIdx.y;
    int i0  = rb * BM;
    bool lower = (i0 < NH);

    const float* Hb = g_H + (size_t)b * NN * DD;
    const float* eb = g_e + b * NN;

    float accA[4][4] = {};
    float accB[4][4] = {};
    float auxA = 0.f, auxB = 0.f;

    for (int kt = 0; kt < NH / KT; kt++) TILE_ITER(accA, auxA)
    for (int kt = NH / KT; kt < NN / KT; kt++) TILE_ITER(accB, auxB)

    if (tid < BM) { auxS[0][tid] = auxA; auxS[1][tid] = auxB; }
    __syncthreads();

    const float* s1 = g_s1 + b * NN;
    const float* s2 = g_s2 + b * NN;

#pragma unroll
    for (int ii = 0; ii < 4; ii++) {
        int r  = ty4 + ii;
        int gi = i0 + r;
        float wA, wB;
        if (lower) {
            // row has two distinct pre-mask values v0 (j<1024), v1 (j>=1024)
            float u0 = s1[2 * gi] + s2[2 * gi];
            float u1 = s1[2 * gi + 1] + s2[2 * gi + 1];
            u0 = u0 > 0.f ? u0 : 0.2f * u0;
            u1 = u1 > 0.f ? u1 : 0.2f * u1;
            float mv = fmaxf(u0, u1);
            float e0 = expf(u0 - mv);
            float e1 = expf(u1 - mv);
            float Z  = auxS[0][r] * e0 + auxS[1][r] * e1;  // c0*e0 + c1*e1
            wA = e0 / Z;
            wB = e1 / Z;
        } else {
            float inv = 1.0f / (auxS[0][r] + auxS[1][r]);  // 1/denominator
            wA = inv;
            wB = inv;
        }
        float4 hv = *(const float4*)&Hb[gi * DD + tx4];
        float4 o;
        o.x = tanhf(wA * accA[ii][0] + wB * accB[ii][0] + bias[tx4 + 0]) + hv.x;
        o.y = tanhf(wA * accA[ii][1] + wB * accB[ii][1] + bias[tx4 + 1]) + hv.y;
        o.z = tanhf(wA * accA[ii][2] + wB * accB[ii][2] + bias[tx4 + 2]) + hv.z;
        o.w = tanhf(wA * accA[ii][3] + wB * accB[ii][3] + bias[tx4 + 3]) + hv.w;
        *(float4*)&out[((size_t)b * NN + gi) * DD + tx4] = o;
    }
}

// ---------------------------------------------------------------------------
extern "C" void kernel_launch(void* const* d_in, const int* in_sizes, int n_in,
                              void* d_out, int out_size) {
    const float* x    = nullptr;
    const int*   adj  = nullptr;
    const float* Wm   = nullptr;
    const float* av   = nullptr;
    const float* bias = nullptr;
    // Map inputs by element count (all unique): x=2097152, adj=4194304,
    // W=8192, a=128, bias=64.
    for (int i = 0; i < n_in; i++) {
        switch (in_sizes[i]) {
            case BB * NN * CC: x    = (const float*)d_in[i]; break;
            case NN * NN:      adj  = (const int*)d_in[i];   break;
            case CC * DD:      Wm   = (const float*)d_in[i]; break;
            case 2 * DD:       av   = (const float*)d_in[i]; break;
            case DD:           bias = (const float*)d_in[i]; break;
            default: break;
        }
    }
    if (!x || !adj || !Wm || !av || !bias) return;
    float* out = (float*)d_out;

    k_hidden<<<BB * NN / 4, 256>>>(x, Wm, av);
    k_prep<<<BB, 256>>>();
    k_main<<<dim3(NN / BM, BB), 256>>>(adj, bias, out);
}

// round 6
// speedup vs baseline: 1.2691x; 1.2691x over previous
#include <cuda_runtime.h>
#include <math.h>

#define BB 8
#define NN 2048
#define CC 128
#define DD 64
#define NH 1024
#define KT 32
#define RBM 128

// Scratch (device globals: no allocation allowed)
__device__ float g_H[BB * NN * DD];        // hidden [B,N,D]
__device__ float g_s1[BB * NN];
__device__ float g_s2[BB * NN];
__device__ float g_e[BB * NN];             // exp(t - max), period-1024 duplicated
__device__ unsigned char g_adj8[NN * NN];  // adj as 0/1 bytes
__device__ float g_w[2][BB][NN];           // per-row softmax weights [wA|wB][b][i]

// ---------------------------------------------------------------------------
// Kernel 1: H = x @ W (64x64 tile, 4x4 micro), s1/s2 folded into epilogue.
// 256 threads. W (32KB) resident in smem; x tile streamed in four 32-row-
// equivalent K-chunks of 8KB each. Total static smem = 40KB (< 48KB limit).
// ---------------------------------------------------------------------------
__global__ __launch_bounds__(256) void k_hidden(const float* __restrict__ x,
                                                const float* __restrict__ Wm,
                                                const float* __restrict__ av) {
    __shared__ float xs[64][32];   // 8KB (one 32-wide K-chunk for 64 rows)
    __shared__ float Ws[CC][DD];   // 32KB
    int tid = threadIdx.x;
    int tx = tid & 15, ty = tid >> 4;
    int tx4 = tx * 4, ty4 = ty * 4;
    int i0 = blockIdx.x * 64;

    const float4* wg = (const float4*)Wm;
    float4* ws4 = (float4*)Ws;
#pragma unroll
    for (int q = 0; q < 8; q++) ws4[tid + q * 256] = wg[tid + q * 256];

    const float4* xg4 = (const float4*)(x + (size_t)i0 * CC);
    float4* xs4 = (float4*)xs;

    float acc[4][4] = {};

#pragma unroll
    for (int kc = 0; kc < 4; kc++) {
        __syncthreads();
        // load x chunk: 64 rows x 32 cols (cols kc*32..kc*32+31) = 512 float4
#pragma unroll
        for (int q = 0; q < 2; q++) {
            int idx = tid + q * 256;      // 0..511
            int row = idx >> 3;           // 0..63
            int c4  = idx & 7;            // 0..7 (8 float4 per row chunk)
            xs4[row * 8 + c4] = xg4[row * 32 + kc * 8 + c4];
        }
        __syncthreads();
#pragma unroll 8
        for (int k = 0; k < 32; k++) {
            int kk = kc * 32 + k;
            float4 bf = *(const float4*)&Ws[kk][tx4];
            float a0 = xs[ty4 + 0][k];
            float a1 = xs[ty4 + 1][k];
            float a2 = xs[ty4 + 2][k];
            float a3 = xs[ty4 + 3][k];
            acc[0][0] = fmaf(a0, bf.x, acc[0][0]);
            acc[0][1] = fmaf(a0, bf.y, acc[0][1]);
            acc[0][2] = fmaf(a0, bf.z, acc[0][2]);
            acc[0][3] = fmaf(a0, bf.w, acc[0][3]);
            acc[1][0] = fmaf(a1, bf.x, acc[1][0]);
            acc[1][1] = fmaf(a1, bf.y, acc[1][1]);
            acc[1][2] = fmaf(a1, bf.z, acc[1][2]);
            acc[1][3] = fmaf(a1, bf.w, acc[1][3]);
            acc[2][0] = fmaf(a2, bf.x, acc[2][0]);
            acc[2][1] = fmaf(a2, bf.y, acc[2][1]);
            acc[2][2] = fmaf(a2, bf.z, acc[2][2]);
            acc[2][3] = fmaf(a2, bf.w, acc[2][3]);
            acc[3][0] = fmaf(a3, bf.x, acc[3][0]);
            acc[3][1] = fmaf(a3, bf.y, acc[3][1]);
            acc[3][2] = fmaf(a3, bf.z, acc[3][2]);
            acc[3][3] = fmaf(a3, bf.w, acc[3][3]);
        }
    }

    float a1v0 = av[tx4 + 0], a1v1 = av[tx4 + 1], a1v2 = av[tx4 + 2], a1v3 = av[tx4 + 3];
    float a2v0 = av[DD + tx4 + 0], a2v1 = av[DD + tx4 + 1], a2v2 = av[DD + tx4 + 2], a2v3 = av[DD + tx4 + 3];

#pragma unroll
    for (int ii = 0; ii < 4; ii++) {
        int row = i0 + ty4 + ii;
        *(float4*)&g_H[(size_t)row * DD + tx4] =
            make_float4(acc[ii][0], acc[ii][1], acc[ii][2], acc[ii][3]);
        float p1 = acc[ii][0] * a1v0 + acc[ii][1] * a1v1 + acc[ii][2] * a1v2 + acc[ii][3] * a1v3;
        float p2 = acc[ii][0] * a2v0 + acc[ii][1] * a2v1 + acc[ii][2] * a2v2 + acc[ii][3] * a2v3;
#pragma unroll
        for (int o = 8; o > 0; o >>= 1) {
            p1 += __shfl_xor_sync(0xffffffffu, p1, o);
            p2 += __shfl_xor_sync(0xffffffffu, p2, o);
        }
        if (tx == 0) { g_s1[row] = p1; g_s2[row] = p2; }
    }
}

// ---------------------------------------------------------------------------
// Kernel 2: per batch, t[j] = lrelu(s1[2j] + s2[2j+1]) (period 1024),
// e[j] = exp(t - max). One block per batch.
// ---------------------------------------------------------------------------
__global__ __launch_bounds__(256) void k_prep() {
    int b = blockIdx.x;
    __shared__ float ts[NH];
    __shared__ float red[256];
    const float* s1 = g_s1 + b * NN;
    const float* s2 = g_s2 + b * NN;
    int tid = threadIdx.x;

    float mx = -1e30f;
    for (int j = tid; j < NH; j += 256) {
        float v = s1[2 * j] + s2[2 * j + 1];
        v = v > 0.f ? v : 0.2f * v;
        ts[j] = v;
        mx = fmaxf(mx, v);
    }
    red[tid] = mx;
    __syncthreads();
    for (int o = 128; o > 0; o >>= 1) {
        if (tid < o) red[tid] = fmaxf(red[tid], red[tid + o]);
        __syncthreads();
    }
    mx = red[0];
    for (int j = tid; j < NH; j += 256) {
        float e = expf(ts[j] - mx);
        g_e[b * NN + j] = e;
        g_e[b * NN + NH + j] = e;
    }
}

// ---------------------------------------------------------------------------
// Kernel 3: per adjacency row i: convert adj->uint8, compute half-counts
// (c0,c1) and, for upper rows, e-weighted denominators per batch; then the
// final per-row softmax weights wA,wB for every batch. One block per row.
// ---------------------------------------------------------------------------
__global__ __launch_bounds__(256) void k_aux(const int* __restrict__ adj) {
    int i = blockIdx.x;
    int tid = threadIdx.x;
    int lane = tid & 31, wid = tid >> 5;
    __shared__ float sc0[8], sc1[8];
    __shared__ float sdb[8][8];   // [warp][batch]
    __shared__ float fc0s, fc1s;
    __shared__ float dtot[8];

    const int4* arow = (const int4*)(adj + (size_t)i * NN);
    uchar4* orow = (uchar4*)(g_adj8 + (size_t)i * NN);
    bool upper = (i >= NH);

    int c0 = 0, c1 = 0;
    float db[8] = {0.f, 0.f, 0.f, 0.f, 0.f, 0.f, 0.f, 0.f};

#pragma unroll
    for (int q = 0; q < 2; q++) {
        int idx4 = tid + q * 256;        // 0..511
        int4 v = arow[idx4];
        uchar4 m;
        m.x = v.x > 0; m.y = v.y > 0; m.z = v.z > 0; m.w = v.w > 0;
        orow[idx4] = m;
        int cnt = m.x + m.y + m.z + m.w;
        int j0 = idx4 * 4;
        if (j0 < NH) c0 += cnt; else c1 += cnt;
        if (upper) {
#pragma unroll
            for (int b = 0; b < 8; b++) {
                float4 ev = *(const float4*)(g_e + b * NN + j0);
                db[b] += (m.x ? ev.x : 0.f) + (m.y ? ev.y : 0.f)
                       + (m.z ? ev.z : 0.f) + (m.w ? ev.w : 0.f);
            }
        }
    }
#pragma unroll
    for (int o = 16; o > 0; o >>= 1) {
        c0 += __shfl_down_sync(0xffffffffu, c0, o);
        c1 += __shfl_down_sync(0xffffffffu, c1, o);
    }
    if (upper) {
#pragma unroll
        for (int b = 0; b < 8; b++)
#pragma unroll
            for (int o = 16; o > 0; o >>= 1)
                db[b] += __shfl_down_sync(0xffffffffu, db[b], o);
    }
    if (lane == 0) {
        sc0[wid] = (float)c0; sc1[wid] = (float)c1;
        if (upper) {
#pragma unroll
            for (int b = 0; b < 8; b++) sdb[wid][b] = db[b];
        }
    }
    __syncthreads();
    if (tid == 0) {
        float t0 = 0.f, t1 = 0.f;
#pragma unroll
        for (int w = 0; w < 8; w++) { t0 += sc0[w]; t1 += sc1[w]; }
        fc0s = t0; fc1s = t1;
    }
    if (upper && tid < 8) {
        float t = 0.f;
#pragma unroll
        for (int w = 0; w < 8; w++) t += sdb[w][tid];
        dtot[tid] = t;
    }
    __syncthreads();
    if (tid < 8) {
        int b = tid;
        float wA, wB;
        if (!upper) {
            float u0 = g_s1[b * NN + 2 * i] + g_s2[b * NN + 2 * i];
            float u1 = g_s1[b * NN + 2 * i + 1] + g_s2[b * NN + 2 * i + 1];
            u0 = u0 > 0.f ? u0 : 0.2f * u0;
            u1 = u1 > 0.f ? u1 : 0.2f * u1;
            float mv = fmaxf(u0, u1);
            float e0 = expf(u0 - mv);
            float e1 = expf(u1 - mv);
            float Z = fc0s * e0 + fc1s * e1;
            wA = e0 / Z;
            wB = e1 / Z;
        } else {
            float inv = 1.f / dtot[b];
            wA = inv;
            wB = inv;
        }
        g_w[0][b][i] = wA;
        g_w[1][b][i] = wB;
    }
}

// ---------------------------------------------------------------------------
// Kernel 4: fused attention GEMM, single accumulator.
// out[b,i,:] = tanh( Sum_j (w_half(i)*adj[i,j]) * (e?*H[b,j,:]) + bias ) + H[b,i,:]
// Tile 128 rows x 64 cols (all of D), 256 threads, 8x4 micro-tile, KT=32,
// register prefetch of next tile's global loads.
// ---------------------------------------------------------------------------
__global__ __launch_bounds__(256) void k_main(const float* __restrict__ bias,
                                              float* __restrict__ out) {
    __shared__ float As[KT][RBM];   // 16KB, [kk][row], pre-scaled by row weight
    __shared__ float Hs[KT][DD];    // 8KB, pre-scaled by e (upper blocks)
    __shared__ float wAs[RBM], wBs[RBM];

    int tid = threadIdx.x;
    int tx = tid & 15, ty = tid >> 4;
    int tx4 = tx * 4, ty8 = ty * 8;
    int b = blockIdx.y;
    int i0 = blockIdx.x * RBM;
    bool upper = (i0 >= NH);

    const float* Hb = g_H + (size_t)b * NN * DD;
    const float4* Hb4 = (const float4*)Hb;
    const float* eb = g_e + b * NN;

    if (tid < RBM) {
        wAs[tid] = g_w[0][b][i0 + tid];
        wBs[tid] = g_w[1][b][i0 + tid];
    }

    int arow = tid & 127;
    int aseg = (tid >> 7) * 16;
    const unsigned char* abase = g_adj8 + (size_t)(i0 + arow) * NN + aseg;
    int hk0 = tid >> 4;   // 0..15
    int hd = tid & 15;

    uint4 pa;
    float4 ph0, ph1;
    float pe0, pe1;
    {
        pa = *(const uint4*)(abase);
        ph0 = Hb4[(hk0) * 16 + hd];
        ph1 = Hb4[(hk0 + 16) * 16 + hd];
        pe0 = upper ? eb[hk0] : 1.f;
        pe1 = upper ? eb[hk0 + 16] : 1.f;
    }

    float acc[8][4];
#pragma unroll
    for (int ii = 0; ii < 8; ii++)
#pragma unroll
        for (int jj = 0; jj < 4; jj++) acc[ii][jj] = 0.f;

    for (int kt = 0; kt < NN / KT; kt++) {
        int j0 = kt * KT;
        __syncthreads();
        // ---- store A tile (expand bytes, scale by row weight) ----
        float wrow = (j0 < NH) ? wAs[arow] : wBs[arow];
        unsigned v;
        v = pa.x;
        As[aseg + 0][arow] = (v & 0x000000ffu) ? wrow : 0.f;
        As[aseg + 1][arow] = (v & 0x0000ff00u) ? wrow : 0.f;
        As[aseg + 2][arow] = (v & 0x00ff0000u) ? wrow : 0.f;
        As[aseg + 3][arow] = (v & 0xff000000u) ? wrow : 0.f;
        v = pa.y;
        As[aseg + 4][arow] = (v & 0x000000ffu) ? wrow : 0.f;
        As[aseg + 5][arow] = (v & 0x0000ff00u) ? wrow : 0.f;
        As[aseg + 6][arow] = (v & 0x00ff0000u) ? wrow : 0.f;
        As[aseg + 7][arow] = (v & 0xff000000u) ? wrow : 0.f;
        v = pa.z;
        As[aseg + 8][arow]  = (v & 0x000000ffu) ? wrow : 0.f;
        As[aseg + 9][arow]  = (v & 0x0000ff00u) ? wrow : 0.f;
        As[aseg + 10][arow] = (v & 0x00ff0000u) ? wrow : 0.f;
        As[aseg + 11][arow] = (v & 0xff000000u) ? wrow : 0.f;
        v = pa.w;
        As[aseg + 12][arow] = (v & 0x000000ffu) ? wrow : 0.f;
        As[aseg + 13][arow] = (v & 0x0000ff00u) ? wrow : 0.f;
        As[aseg + 14][arow] = (v & 0x00ff0000u) ? wrow : 0.f;
        As[aseg + 15][arow] = (v & 0xff000000u) ? wrow : 0.f;
        // ---- store H tile (scale by e for upper blocks) ----
        *(float4*)&Hs[hk0][hd * 4] =
            make_float4(ph0.x * pe0, ph0.y * pe0, ph0.z * pe0, ph0.w * pe0);
        *(float4*)&Hs[hk0 + 16][hd * 4] =
            make_float4(ph1.x * pe1, ph1.y * pe1, ph1.z * pe1, ph1.w * pe1);
        __syncthreads();
        // ---- prefetch next tile into registers (overlaps GEMM) ----
        if (kt + 1 < NN / KT) {
            int jn = j0 + KT;
            pa = *(const uint4*)(abase + jn);
            ph0 = Hb4[(jn + hk0) * 16 + hd];
            ph1 = Hb4[(jn + hk0 + 16) * 16 + hd];
            pe0 = upper ? eb[jn + hk0] : 1.f;
            pe1 = upper ? eb[jn + hk0 + 16] : 1.f;
        }
        // ---- GEMM over smem tile ----
#pragma unroll 8
        for (int kk = 0; kk < KT; kk++) {
            float4 av0 = *(const float4*)&As[kk][ty8];
            float4 av1 = *(const float4*)&As[kk][ty8 + 4];
            float4 bf = *(const float4*)&Hs[kk][tx4];
            acc[0][0] = fmaf(av0.x, bf.x, acc[0][0]);
            acc[0][1] = fmaf(av0.x, bf.y, acc[0][1]);
            acc[0][2] = fmaf(av0.x, bf.z, acc[0][2]);
            acc[0][3] = fmaf(av0.x, bf.w, acc[0][3]);
            acc[1][0] = fmaf(av0.y, bf.x, acc[1][0]);
            acc[1][1] = fmaf(av0.y, bf.y, acc[1][1]);
            acc[1][2] = fmaf(av0.y, bf.z, acc[1][2]);
            acc[1][3] = fmaf(av0.y, bf.w, acc[1][3]);
            acc[2][0] = fmaf(av0.z, bf.x, acc[2][0]);
            acc[2][1] = fmaf(av0.z, bf.y, acc[2][1]);
            acc[2][2] = fmaf(av0.z, bf.z, acc[2][2]);
            acc[2][3] = fmaf(av0.z, bf.w, acc[2][3]);
            acc[3][0] = fmaf(av0.w, bf.x, acc[3][0]);
            acc[3][1] = fmaf(av0.w, bf.y, acc[3][1]);
            acc[3][2] = fmaf(av0.w, bf.z, acc[3][2]);
            acc[3][3] = fmaf(av0.w, bf.w, acc[3][3]);
            acc[4][0] = fmaf(av1.x, bf.x, acc[4][0]);
            acc[4][1] = fmaf(av1.x, bf.y, acc[4][1]);
            acc[4][2] = fmaf(av1.x, bf.z, acc[4][2]);
            acc[4][3] = fmaf(av1.x, bf.w, acc[4][3]);
            acc[5][0] = fmaf(av1.y, bf.x, acc[5][0]);
            acc[5][1] = fmaf(av1.y, bf.y, acc[5][1]);
            acc[5][2] = fmaf(av1.y, bf.z, acc[5][2]);
            acc[5][3] = fmaf(av1.y, bf.w, acc[5][3]);
            acc[6][0] = fmaf(av1.z, bf.x, acc[6][0]);
            acc[6][1] = fmaf(av1.z, bf.y, acc[6][1]);
            acc[6][2] = fmaf(av1.z, bf.z, acc[6][2]);
            acc[6][3] = fmaf(av1.z, bf.w, acc[6][3]);
            acc[7][0] = fmaf(av1.w, bf.x, acc[7][0]);
            acc[7][1] = fmaf(av1.w, bf.y, acc[7][1]);
            acc[7][2] = fmaf(av1.w, bf.z, acc[7][2]);
            acc[7][3] = fmaf(av1.w, bf.w, acc[7][3]);
        }
    }

    // ---- epilogue: tanh(acc + bias) + H ----
    float4 bv = *(const float4*)&bias[tx4];
#pragma unroll
    for (int ii = 0; ii < 8; ii++) {
        int gi = i0 + ty8 + ii;
        float4 hv = Hb4[gi * 16 + tx];
        float4 o;
        o.x = tanhf(acc[ii][0] + bv.x) + hv.x;
        o.y = tanhf(acc[ii][1] + bv.y) + hv.y;
        o.z = tanhf(acc[ii][2] + bv.z) + hv.z;
        o.w = tanhf(acc[ii][3] + bv.w) + hv.w;
        *(float4*)&out[((size_t)b * NN + gi) * DD + tx4] = o;
    }
}

// ---------------------------------------------------------------------------
extern "C" void kernel_launch(void* const* d_in, const int* in_sizes, int n_in,
                              void* d_out, int out_size) {
    const float* x    = nullptr;
    const int*   adj  = nullptr;
    const float* Wm   = nullptr;
    const float* av   = nullptr;
    const float* bias = nullptr;
    for (int i = 0; i < n_in; i++) {
        switch (in_sizes[i]) {
            case BB * NN * CC: x    = (const float*)d_in[i]; break;
            case NN * NN:      adj  = (const int*)d_in[i];   break;
            case CC * DD:      Wm   = (const float*)d_in[i]; break;
            case 2 * DD:       av   = (const float*)d_in[i]; break;
            case DD:           bias = (const float*)d_in[i]; break;
            default: break;
        }
    }
    if (!x || !adj || !Wm || !av || !bias) return;
    float* out = (float*)d_out;

    k_hidden<<<BB * NN / 64, 256>>>(x, Wm, av);
    k_prep<<<BB, 256>>>();
    k_aux<<<NN, 256>>>(adj);
    k_main<<<dim3(NN / RBM, BB), 256>>>(bias, out);
}

// round 8
// speedup vs baseline: 3.3847x; 2.6670x over previous
#include <cuda_runtime.h>
#include <cuda_bf16.h>
#include <math.h>

#define BB 8
#define NN 2048
#define CC 128
#define DD 64
#define NH 1024
#define ASTR 72
#define BSTR 72

// Scratch (device globals: no allocation allowed)
__device__ float g_H[BB * NN * DD];        // hidden [B,N,D] fp32
__device__ float g_s1[BB * NN];
__device__ float g_s2[BB * NN];
__device__ float g_e[BB * NN];             // exp(t - max), period-1024 duplicated
__device__ unsigned char g_adj8[NN * NN];  // adj as 0/1 bytes
__device__ float g_w[2][BB][NN];           // per-row softmax weights [wA|wB][b][i]
__device__ __nv_bfloat16 g_Hv[2][BB * NN * DD];  // [0]=bf16(H), [1]=bf16(e*H)

// ---------------------------------------------------------------------------
// Kernel 1: H = x @ W (64x64 tile, 4x4 micro), s1/s2 folded into epilogue.
// ---------------------------------------------------------------------------
__global__ __launch_bounds__(256) void k_hidden(const float* __restrict__ x,
                                                const float* __restrict__ Wm,
                                                const float* __restrict__ av) {
    __shared__ float xs[64][32];   // 8KB
    __shared__ float Ws[CC][DD];   // 32KB
    int tid = threadIdx.x;
    int tx = tid & 15, ty = tid >> 4;
    int tx4 = tx * 4, ty4 = ty * 4;
    int i0 = blockIdx.x * 64;

    const float4* wg = (const float4*)Wm;
    float4* ws4 = (float4*)Ws;
#pragma unroll
    for (int q = 0; q < 8; q++) ws4[tid + q * 256] = wg[tid + q * 256];

    const float4* xg4 = (const float4*)(x + (size_t)i0 * CC);
    float4* xs4 = (float4*)xs;

    float acc[4][4] = {};

#pragma unroll
    for (int kc = 0; kc < 4; kc++) {
        __syncthreads();
#pragma unroll
        for (int q = 0; q < 2; q++) {
            int idx = tid + q * 256;
            int row = idx >> 3;
            int c4  = idx & 7;
            xs4[row * 8 + c4] = xg4[row * 32 + kc * 8 + c4];
        }
        __syncthreads();
#pragma unroll 8
        for (int k = 0; k < 32; k++) {
            int kk = kc * 32 + k;
            float4 bf = *(const float4*)&Ws[kk][tx4];
            float a0 = xs[ty4 + 0][k];
            float a1 = xs[ty4 + 1][k];
            float a2 = xs[ty4 + 2][k];
            float a3 = xs[ty4 + 3][k];
            acc[0][0] = fmaf(a0, bf.x, acc[0][0]);
            acc[0][1] = fmaf(a0, bf.y, acc[0][1]);
            acc[0][2] = fmaf(a0, bf.z, acc[0][2]);
            acc[0][3] = fmaf(a0, bf.w, acc[0][3]);
            acc[1][0] = fmaf(a1, bf.x, acc[1][0]);
            acc[1][1] = fmaf(a1, bf.y, acc[1][1]);
            acc[1][2] = fmaf(a1, bf.z, acc[1][2]);
            acc[1][3] = fmaf(a1, bf.w, acc[1][3]);
            acc[2][0] = fmaf(a2, bf.x, acc[2][0]);
            acc[2][1] = fmaf(a2, bf.y, acc[2][1]);
            acc[2][2] = fmaf(a2, bf.z, acc[2][2]);
            acc[2][3] = fmaf(a2, bf.w, acc[2][3]);
            acc[3][0] = fmaf(a3, bf.x, acc[3][0]);
            acc[3][1] = fmaf(a3, bf.y, acc[3][1]);
            acc[3][2] = fmaf(a3, bf.z, acc[3][2]);
            acc[3][3] = fmaf(a3, bf.w, acc[3][3]);
        }
    }

    float a1v0 = av[tx4 + 0], a1v1 = av[tx4 + 1], a1v2 = av[tx4 + 2], a1v3 = av[tx4 + 3];
    float a2v0 = av[DD + tx4 + 0], a2v1 = av[DD + tx4 + 1], a2v2 = av[DD + tx4 + 2], a2v3 = av[DD + tx4 + 3];

#pragma unroll
    for (int ii = 0; ii < 4; ii++) {
        int row = i0 + ty4 + ii;
        *(float4*)&g_H[(size_t)row * DD + tx4] =
            make_float4(acc[ii][0], acc[ii][1], acc[ii][2], acc[ii][3]);
        float p1 = acc[ii][0] * a1v0 + acc[ii][1] * a1v1 + acc[ii][2] * a1v2 + acc[ii][3] * a1v3;
        float p2 = acc[ii][0] * a2v0 + acc[ii][1] * a2v1 + acc[ii][2] * a2v2 + acc[ii][3] * a2v3;
#pragma unroll
        for (int o = 8; o > 0; o >>= 1) {
            p1 += __shfl_xor_sync(0xffffffffu, p1, o);
            p2 += __shfl_xor_sync(0xffffffffu, p2, o);
        }
        if (tx == 0) { g_s1[row] = p1; g_s2[row] = p2; }
    }
}

// ---------------------------------------------------------------------------
// Kernel 2: e[j] = exp(lrelu(s1[2j]+s2[2j+1]) - max) per batch, period 1024.
// ---------------------------------------------------------------------------
__global__ __launch_bounds__(256) void k_prep() {
    int b = blockIdx.x;
    __shared__ float ts[NH];
    __shared__ float red[256];
    const float* s1 = g_s1 + b * NN;
    const float* s2 = g_s2 + b * NN;
    int tid = threadIdx.x;

    float mx = -1e30f;
    for (int j = tid; j < NH; j += 256) {
        float v = s1[2 * j] + s2[2 * j + 1];
        v = v > 0.f ? v : 0.2f * v;
        ts[j] = v;
        mx = fmaxf(mx, v);
    }
    red[tid] = mx;
    __syncthreads();
    for (int o = 128; o > 0; o >>= 1) {
        if (tid < o) red[tid] = fmaxf(red[tid], red[tid + o]);
        __syncthreads();
    }
    mx = red[0];
    for (int j = tid; j < NH; j += 256) {
        float e = expf(ts[j] - mx);
        g_e[b * NN + j] = e;
        g_e[b * NN + NH + j] = e;
    }
}

// ---------------------------------------------------------------------------
// Kernel 3: adj->uint8, per-row half-counts / e-denominators, final wA/wB.
// ---------------------------------------------------------------------------
__global__ __launch_bounds__(256) void k_aux(const int* __restrict__ adj) {
    int i = blockIdx.x;
    int tid = threadIdx.x;
    int lane = tid & 31, wid = tid >> 5;
    __shared__ float sc0[8], sc1[8];
    __shared__ float sdb[8][8];
    __shared__ float fc0s, fc1s;
    __shared__ float dtot[8];

    const int4* arow = (const int4*)(adj + (size_t)i * NN);
    uchar4* orow = (uchar4*)(g_adj8 + (size_t)i * NN);
    bool upper = (i >= NH);

    int c0 = 0, c1 = 0;
    float db[8] = {0.f, 0.f, 0.f, 0.f, 0.f, 0.f, 0.f, 0.f};

#pragma unroll
    for (int q = 0; q < 2; q++) {
        int idx4 = tid + q * 256;
        int4 v = arow[idx4];
        uchar4 m;
        m.x = v.x > 0; m.y = v.y > 0; m.z = v.z > 0; m.w = v.w > 0;
        orow[idx4] = m;
        int cnt = m.x + m.y + m.z + m.w;
        int j0 = idx4 * 4;
        if (j0 < NH) c0 += cnt; else c1 += cnt;
        if (upper) {
#pragma unroll
            for (int b = 0; b < 8; b++) {
                float4 ev = *(const float4*)(g_e + b * NN + j0);
                db[b] += (m.x ? ev.x : 0.f) + (m.y ? ev.y : 0.f)
                       + (m.z ? ev.z : 0.f) + (m.w ? ev.w : 0.f);
            }
        }
    }
#pragma unroll
    for (int o = 16; o > 0; o >>= 1) {
        c0 += __shfl_down_sync(0xffffffffu, c0, o);
        c1 += __shfl_down_sync(0xffffffffu, c1, o);
    }
    if (upper) {
#pragma unroll
        for (int b = 0; b < 8; b++)
#pragma unroll
            for (int o = 16; o > 0; o >>= 1)
                db[b] += __shfl_down_sync(0xffffffffu, db[b], o);
    }
    if (lane == 0) {
        sc0[wid] = (float)c0; sc1[wid] = (float)c1;
        if (upper) {
#pragma unroll
            for (int b = 0; b < 8; b++) sdb[wid][b] = db[b];
        }
    }
    __syncthreads();
    if (tid == 0) {
        float t0 = 0.f, t1 = 0.f;
#pragma unroll
        for (int w = 0; w < 8; w++) { t0 += sc0[w]; t1 += sc1[w]; }
        fc0s = t0; fc1s = t1;
    }
    if (upper && tid < 8) {
        float t = 0.f;
#pragma unroll
        for (int w = 0; w < 8; w++) t += sdb[w][tid];
        dtot[tid] = t;
    }
    __syncthreads();
    if (tid < 8) {
        int b = tid;
        float wA, wB;
        if (!upper) {
            float u0 = g_s1[b * NN + 2 * i] + g_s2[b * NN + 2 * i];
            float u1 = g_s1[b * NN + 2 * i + 1] + g_s2[b * NN + 2 * i + 1];
            u0 = u0 > 0.f ? u0 : 0.2f * u0;
            u1 = u1 > 0.f ? u1 : 0.2f * u1;
            float mv = fmaxf(u0, u1);
            float e0 = expf(u0 - mv);
            float e1 = expf(u1 - mv);
            float Z = fc0s * e0 + fc1s * e1;
            wA = e0 / Z;
            wB = e1 / Z;
        } else {
            float inv = 1.f / dtot[b];
            wA = inv;
            wB = inv;
        }
        g_w[0][b][i] = wA;
        g_w[1][b][i] = wB;
    }
}

// ---------------------------------------------------------------------------
// Kernel 3.5: pack bf16 B operands: g_Hv[0]=bf16(H), g_Hv[1]=bf16(e*H).
// ---------------------------------------------------------------------------
__device__ __forceinline__ unsigned pack2bf(float a, float b) {
    __nv_bfloat162 t = __floats2bfloat162_rn(a, b);
    return *(unsigned*)&t;
}

__global__ __launch_bounds__(256) void k_conv() {
    int idx = blockIdx.x * 256 + threadIdx.x;   // one float4 per thread
    int base = idx * 4;
    float4 h = *(const float4*)&g_H[base];
    float e = g_e[base >> 6];                   // (b*NN + j)
    *(uint2*)&g_Hv[0][base] = make_uint2(pack2bf(h.x, h.y), pack2bf(h.z, h.w));
    *(uint2*)&g_Hv[1][base] = make_uint2(pack2bf(h.x * e, h.y * e),
                                         pack2bf(h.z * e, h.w * e));
}

// ---------------------------------------------------------------------------
// Kernel 4: tensor-core fused attention GEMM.
// out[b,i,:] = tanh( wA*Sum_{j<1024} adj*Bv + wB*Sum_{j>=1024} adj*Bv + bias ) + H
// Bv = H (lower row-blocks) or e*H (upper row-blocks), bf16.
// Block: 128 rows x 64 cols, 256 threads = 8 warps (4 m x 2 n), warp 32x32.
// mma.sync m16n8k16 bf16 -> fp32, two accumulator sets split at K=1024.
// ---------------------------------------------------------------------------
__device__ __forceinline__ unsigned exp2b(unsigned v) {
    // bytes b0,b1 (bits 0..15, values 0/1) -> packed bf16 pair (0 or 1.0f)
    return (v & 1u) * 0x3F80u | ((v >> 8) & 1u) * 0x3F800000u;
}

__device__ __forceinline__ void st_expand(uint4 v, __nv_bfloat16* dst) {
    uint4 d0 = make_uint4(exp2b(v.x & 0xFFFFu), exp2b(v.x >> 16),
                          exp2b(v.y & 0xFFFFu), exp2b(v.y >> 16));
    uint4 d1 = make_uint4(exp2b(v.z & 0xFFFFu), exp2b(v.z >> 16),
                          exp2b(v.w & 0xFFFFu), exp2b(v.w >> 16));
    ((uint4*)dst)[0] = d0;
    ((uint4*)dst)[1] = d1;
}

#define LDSM4(R, ADDR)                                                         \
    asm volatile("ldmatrix.sync.aligned.m8n8.x4.shared.b16 {%0,%1,%2,%3}, [%4];" \
                 : "=r"(R[0]), "=r"(R[1]), "=r"(R[2]), "=r"(R[3]) : "r"(ADDR))

#define LDSM4T(R, ADDR)                                                        \
    asm volatile("ldmatrix.sync.aligned.m8n8.x4.trans.shared.b16 {%0,%1,%2,%3}, [%4];" \
                 : "=r"(R[0]), "=r"(R[1]), "=r"(R[2]), "=r"(R[3]) : "r"(ADDR))

#define MMA16816(C, AR, B0, B1)                                                \
    asm volatile(                                                              \
        "mma.sync.aligned.m16n8k16.row.col.f32.bf16.bf16.f32 "                 \
        "{%0,%1,%2,%3}, {%4,%5,%6,%7}, {%8,%9}, {%0,%1,%2,%3};"                \
        : "+f"(C[0]), "+f"(C[1]), "+f"(C[2]), "+f"(C[3])                       \
        : "r"(AR[0]), "r"(AR[1]), "r"(AR[2]), "r"(AR[3]), "r"(B0), "r"(B1))

#define TILE_BODY(ACC)                                                         \
    {                                                                          \
        __syncthreads();                                                       \
        st_expand(pa0, &As[arA]);                                              \
        st_expand(pa1, &As[arA + 16]);                                         \
        *(uint4*)&Bs[brB] = pb0;                                               \
        *(uint4*)&Bs[brB + 32] = pb1;                                          \
        __syncthreads();                                                       \
        if (kt + 1 < 32) {                                                     \
            const unsigned char* ap = aGbase + (kt + 1) * 64;                  \
            pa0 = *(const uint4*)ap;                                           \
            pa1 = *(const uint4*)(ap + 16);                                    \
            const uint4* bp = (const uint4*)(HvB + ((kt + 1) * 64 + br) * DD); \
            pb0 = bp[bi1];                                                     \
            pb1 = bp[bi2];                                                     \
        }                                                                      \
        _Pragma("unroll")                                                      \
        for (int k16 = 0; k16 < 4; k16++) {                                    \
            unsigned a0[4], a1[4], f0[4], f1[4];                               \
            LDSM4(a0, aA0 + k16 * 32);                                         \
            LDSM4(a1, aA1 + k16 * 32);                                         \
            LDSM4T(f0, aB0 + k16 * 16 * BSTR * 2);                             \
            LDSM4T(f1, aB1 + k16 * 16 * BSTR * 2);                             \
            MMA16816(ACC[0][0], a0, f0[0], f0[1]);                             \
            MMA16816(ACC[0][1], a0, f0[2], f0[3]);                             \
            MMA16816(ACC[0][2], a0, f1[0], f1[1]);                             \
            MMA16816(ACC[0][3], a0, f1[2], f1[3]);                             \
            MMA16816(ACC[1][0], a1, f0[0], f0[1]);                             \
            MMA16816(ACC[1][1], a1, f0[2], f0[3]);                             \
            MMA16816(ACC[1][2], a1, f1[0], f1[1]);                             \
            MMA16816(ACC[1][3], a1, f1[2], f1[3]);                             \
        }                                                                      \
    }

__global__ __launch_bounds__(256) void k_main(const float* __restrict__ bias,
                                              float* __restrict__ out) {
    __shared__ __align__(16) __nv_bfloat16 As[128 * ASTR];  // ~18KB [m][k]
    __shared__ __align__(16) __nv_bfloat16 Bs[64 * BSTR];   // ~9KB  [k][n]
    __shared__ float wAs[128], wBs[128];

    int tid = threadIdx.x;
    int lane = tid & 31, warp = tid >> 5;
    int wm = warp & 3, wn = warp >> 2;
    int b = blockIdx.y;
    int i0 = blockIdx.x * 128;
    bool upper = (i0 >= NH);

    if (tid < 128) {
        wAs[tid] = g_w[0][b][i0 + tid];
        wBs[tid] = g_w[1][b][i0 + tid];
    }

    const __nv_bfloat16* HvB = g_Hv[upper ? 1 : 0] + (size_t)b * NN * DD;

    // A staging: 128 rows x 64 bytes per tile; thread -> (row, 32-byte half)
    int ar = tid >> 1;
    int ak = (tid & 1) * 32;
    int arA = ar * ASTR + ak;
    const unsigned char* aGbase = g_adj8 + (size_t)(i0 + ar) * NN + ak;

    // B staging: 64 rows x 128 bytes; thread -> (row, two uint4 slots)
    int br = tid >> 2;
    int bi1 = tid & 3, bi2 = bi1 + 4;
    int brB = br * BSTR + bi1 * 8;

    unsigned asb = (unsigned)__cvta_generic_to_shared(As);
    unsigned bsb = (unsigned)__cvta_generic_to_shared(Bs);
    unsigned aA0 = asb + (unsigned)(((wm * 32 + (lane & 15)) * ASTR + (lane >> 4) * 8) * 2);
    unsigned aA1 = aA0 + 16 * ASTR * 2;
    unsigned aB0 = bsb + (unsigned)(((lane & 15) * BSTR + wn * 32 + (lane >> 4) * 8) * 2);
    unsigned aB1 = aB0 + 32;

    uint4 pa0 = *(const uint4*)aGbase;
    uint4 pa1 = *(const uint4*)(aGbase + 16);
    const uint4* bp0 = (const uint4*)(HvB + br * DD);
    uint4 pb0 = bp0[bi1], pb1 = bp0[bi2];

    float accLo[2][4][4] = {};
    float accHi[2][4][4] = {};

    for (int kt = 0; kt < 16; kt++) TILE_BODY(accLo);
    for (int kt = 16; kt < 32; kt++) TILE_BODY(accHi);

    // epilogue: out = tanh(wA*accLo + wB*accHi + bias) + H
    int gID = lane >> 2, tig = lane & 3;
#pragma unroll
    for (int mt = 0; mt < 2; mt++) {
#pragma unroll
        for (int nt = 0; nt < 4; nt++) {
            int c = wn * 32 + nt * 8 + tig * 2;
            float bx = bias[c], by = bias[c + 1];
#pragma unroll
            for (int hseg = 0; hseg < 2; hseg++) {
                int r = wm * 32 + mt * 16 + gID + hseg * 8;
                float wa = wAs[r], wb = wBs[r];
                int ci = hseg * 2;
                float vx = wa * accLo[mt][nt][ci]     + wb * accHi[mt][nt][ci]     + bx;
                float vy = wa * accLo[mt][nt][ci + 1] + wb * accHi[mt][nt][ci + 1] + by;
                size_t o = ((size_t)b * NN + i0 + r) * DD + c;
                float2 h2 = *(const float2*)&g_H[o];
                float2 ov;
                ov.x = tanhf(vx) + h2.x;
                ov.y = tanhf(vy) + h2.y;
                *(float2*)&out[o] = ov;
            }
        }
    }
}

// ---------------------------------------------------------------------------
extern "C" void kernel_launch(void* const* d_in, const int* in_sizes, int n_in,
                              void* d_out, int out_size) {
    const float* x    = nullptr;
    const int*   adj  = nullptr;
    const float* Wm   = nullptr;
    const float* av   = nullptr;
    const float* bias = nullptr;
    for (int i = 0; i < n_in; i++) {
        switch (in_sizes[i]) {
            case BB * NN * CC: x    = (const float*)d_in[i]; break;
            case NN * NN:      adj  = (const int*)d_in[i];   break;
            case CC * DD:      Wm   = (const float*)d_in[i]; break;
            case 2 * DD:       av   = (const float*)d_in[i]; break;
            case DD:           bias = (const float*)d_in[i]; break;
            default: break;
        }
    }
    if (!x || !adj || !Wm || !av || !bias) return;
    float* out = (float*)d_out;

    k_hidden<<<BB * NN / 64, 256>>>(x, Wm, av);
    k_prep<<<BB, 256>>>();
    k_aux<<<NN, 256>>>(adj);
    k_conv<<<(BB * NN * DD) / 1024, 256>>>();
    k_main<<<dim3(NN / 128, BB), 256>>>(bias, out);
}

// round 9
// speedup vs baseline: 3.4441x; 1.0175x over previous
#include <cuda_runtime.h>
#include <cuda_bf16.h>
#include <math.h>

#define BB 8
#define NN 2048
#define CC 128
#define DD 64
#define NH 1024
#define ASTR 72
#define BSTR 72

// dynamic smem layout for k_main (bytes)
#define A_BUF_BYTES (128 * ASTR * 2)          // 18432
#define B_BUF_BYTES (64 * BSTR * 2)           // 9216
#define B_BASE_OFF  (2 * A_BUF_BYTES)         // 36864
#define DSMEM_BYTES (2 * A_BUF_BYTES + 2 * B_BUF_BYTES)  // 55296

// Scratch (device globals: no allocation allowed)
__device__ float g_H[BB * NN * DD];        // hidden [B,N,D] fp32
__device__ float g_s1[BB * NN];
__device__ float g_s2[BB * NN];
__device__ float g_e[BB * NN];             // exp(t - max), period-1024 duplicated
__device__ unsigned char g_adj8[NN * NN];  // adj as 0/1 bytes
__device__ float g_w[2][BB][NN];           // per-row softmax weights [wA|wB][b][i]
__device__ __nv_bfloat16 g_Hv[2][BB * NN * DD];  // [0]=bf16(H), [1]=bf16(e*H)

__device__ __forceinline__ unsigned pack2bf(float a, float b) {
    __nv_bfloat162 t = __floats2bfloat162_rn(a, b);
    return *(unsigned*)&t;
}

// ---------------------------------------------------------------------------
// Kernel 1: H = x @ W (64x64 tile, 4x4 micro); epilogue also writes
// g_Hv[0]=bf16(H) and folds the s1/s2 dot products.
// ---------------------------------------------------------------------------
__global__ __launch_bounds__(256) void k_hidden(const float* __restrict__ x,
                                                const float* __restrict__ Wm,
                                                const float* __restrict__ av) {
    __shared__ float xs[64][32];   // 8KB
    __shared__ float Ws[CC][DD];   // 32KB
    int tid = threadIdx.x;
    int tx = tid & 15, ty = tid >> 4;
    int tx4 = tx * 4, ty4 = ty * 4;
    int i0 = blockIdx.x * 64;

    const float4* wg = (const float4*)Wm;
    float4* ws4 = (float4*)Ws;
#pragma unroll
    for (int q = 0; q < 8; q++) ws4[tid + q * 256] = wg[tid + q * 256];

    const float4* xg4 = (const float4*)(x + (size_t)i0 * CC);
    float4* xs4 = (float4*)xs;

    float acc[4][4] = {};

#pragma unroll
    for (int kc = 0; kc < 4; kc++) {
        __syncthreads();
#pragma unroll
        for (int q = 0; q < 2; q++) {
            int idx = tid + q * 256;
            int row = idx >> 3;
            int c4  = idx & 7;
            xs4[row * 8 + c4] = xg4[row * 32 + kc * 8 + c4];
        }
        __syncthreads();
#pragma unroll 8
        for (int k = 0; k < 32; k++) {
            int kk = kc * 32 + k;
            float4 bf = *(const float4*)&Ws[kk][tx4];
            float a0 = xs[ty4 + 0][k];
            float a1 = xs[ty4 + 1][k];
            float a2 = xs[ty4 + 2][k];
            float a3 = xs[ty4 + 3][k];
            acc[0][0] = fmaf(a0, bf.x, acc[0][0]);
            acc[0][1] = fmaf(a0, bf.y, acc[0][1]);
            acc[0][2] = fmaf(a0, bf.z, acc[0][2]);
            acc[0][3] = fmaf(a0, bf.w, acc[0][3]);
            acc[1][0] = fmaf(a1, bf.x, acc[1][0]);
            acc[1][1] = fmaf(a1, bf.y, acc[1][1]);
            acc[1][2] = fmaf(a1, bf.z, acc[1][2]);
            acc[1][3] = fmaf(a1, bf.w, acc[1][3]);
            acc[2][0] = fmaf(a2, bf.x, acc[2][0]);
            acc[2][1] = fmaf(a2, bf.y, acc[2][1]);
            acc[2][2] = fmaf(a2, bf.z, acc[2][2]);
            acc[2][3] = fmaf(a2, bf.w, acc[2][3]);
            acc[3][0] = fmaf(a3, bf.x, acc[3][0]);
            acc[3][1] = fmaf(a3, bf.y, acc[3][1]);
            acc[3][2] = fmaf(a3, bf.z, acc[3][2]);
            acc[3][3] = fmaf(a3, bf.w, acc[3][3]);
        }
    }

    float a1v0 = av[tx4 + 0], a1v1 = av[tx4 + 1], a1v2 = av[tx4 + 2], a1v3 = av[tx4 + 3];
    float a2v0 = av[DD + tx4 + 0], a2v1 = av[DD + tx4 + 1], a2v2 = av[DD + tx4 + 2], a2v3 = av[DD + tx4 + 3];

#pragma unroll
    for (int ii = 0; ii < 4; ii++) {
        int row = i0 + ty4 + ii;
        *(float4*)&g_H[(size_t)row * DD + tx4] =
            make_float4(acc[ii][0], acc[ii][1], acc[ii][2], acc[ii][3]);
        *(uint2*)&g_Hv[0][(size_t)row * DD + tx4] =
            make_uint2(pack2bf(acc[ii][0], acc[ii][1]), pack2bf(acc[ii][2], acc[ii][3]));
        float p1 = acc[ii][0] * a1v0 + acc[ii][1] * a1v1 + acc[ii][2] * a1v2 + acc[ii][3] * a1v3;
        float p2 = acc[ii][0] * a2v0 + acc[ii][1] * a2v1 + acc[ii][2] * a2v2 + acc[ii][3] * a2v3;
#pragma unroll
        for (int o = 8; o > 0; o >>= 1) {
            p1 += __shfl_xor_sync(0xffffffffu, p1, o);
            p2 += __shfl_xor_sync(0xffffffffu, p2, o);
        }
        if (tx == 0) { g_s1[row] = p1; g_s2[row] = p2; }
    }
}

// ---------------------------------------------------------------------------
// Kernel 2: e[j] = exp(lrelu(s1[2j]+s2[2j+1]) - max) per batch, period 1024.
// ---------------------------------------------------------------------------
__global__ __launch_bounds__(256) void k_prep() {
    int b = blockIdx.x;
    __shared__ float ts[NH];
    __shared__ float red[256];
    const float* s1 = g_s1 + b * NN;
    const float* s2 = g_s2 + b * NN;
    int tid = threadIdx.x;

    float mx = -1e30f;
    for (int j = tid; j < NH; j += 256) {
        float v = s1[2 * j] + s2[2 * j + 1];
        v = v > 0.f ? v : 0.2f * v;
        ts[j] = v;
        mx = fmaxf(mx, v);
    }
    red[tid] = mx;
    __syncthreads();
    for (int o = 128; o > 0; o >>= 1) {
        if (tid < o) red[tid] = fmaxf(red[tid], red[tid + o]);
        __syncthreads();
    }
    mx = red[0];
    for (int j = tid; j < NH; j += 256) {
        float e = expf(ts[j] - mx);
        g_e[b * NN + j] = e;
        g_e[b * NN + NH + j] = e;
    }
}

// ---------------------------------------------------------------------------
// Kernel 3: adj->uint8, per-row half-counts / e-denominators, final wA/wB.
// ---------------------------------------------------------------------------
__global__ __launch_bounds__(256) void k_aux(const int* __restrict__ adj) {
    int i = blockIdx.x;
    int tid = threadIdx.x;
    int lane = tid & 31, wid = tid >> 5;
    __shared__ float sc0[8], sc1[8];
    __shared__ float sdb[8][8];
    __shared__ float fc0s, fc1s;
    __shared__ float dtot[8];

    const int4* arow = (const int4*)(adj + (size_t)i * NN);
    uchar4* orow = (uchar4*)(g_adj8 + (size_t)i * NN);
    bool upper = (i >= NH);

    int c0 = 0, c1 = 0;
    float db[8] = {0.f, 0.f, 0.f, 0.f, 0.f, 0.f, 0.f, 0.f};

#pragma unroll
    for (int q = 0; q < 2; q++) {
        int idx4 = tid + q * 256;
        int4 v = arow[idx4];
        uchar4 m;
        m.x = v.x > 0; m.y = v.y > 0; m.z = v.z > 0; m.w = v.w > 0;
        orow[idx4] = m;
        int cnt = m.x + m.y + m.z + m.w;
        int j0 = idx4 * 4;
        if (j0 < NH) c0 += cnt; else c1 += cnt;
        if (upper) {
#pragma unroll
            for (int b = 0; b < 8; b++) {
                float4 ev = *(const float4*)(g_e + b * NN + j0);
                db[b] += (m.x ? ev.x : 0.f) + (m.y ? ev.y : 0.f)
                       + (m.z ? ev.z : 0.f) + (m.w ? ev.w : 0.f);
            }
        }
    }
#pragma unroll
    for (int o = 16; o > 0; o >>= 1) {
        c0 += __shfl_down_sync(0xffffffffu, c0, o);
        c1 += __shfl_down_sync(0xffffffffu, c1, o);
    }
    if (upper) {
#pragma unroll
        for (int b = 0; b < 8; b++)
#pragma unroll
            for (int o = 16; o > 0; o >>= 1)
                db[b] += __shfl_down_sync(0xffffffffu, db[b], o);
    }
    if (lane == 0) {
        sc0[wid] = (float)c0; sc1[wid] = (float)c1;
        if (upper) {
#pragma unroll
            for (int b = 0; b < 8; b++) sdb[wid][b] = db[b];
        }
    }
    __syncthreads();
    if (tid == 0) {
        float t0 = 0.f, t1 = 0.f;
#pragma unroll
        for (int w = 0; w < 8; w++) { t0 += sc0[w]; t1 += sc1[w]; }
        fc0s = t0; fc1s = t1;
    }
    if (upper && tid < 8) {
        float t = 0.f;
#pragma unroll
        for (int w = 0; w < 8; w++) t += sdb[w][tid];
        dtot[tid] = t;
    }
    __syncthreads();
    if (tid < 8) {
        int b = tid;
        float wA, wB;
        if (!upper) {
            float u0 = g_s1[b * NN + 2 * i] + g_s2[b * NN + 2 * i];
            float u1 = g_s1[b * NN + 2 * i + 1] + g_s2[b * NN + 2 * i + 1];
            u0 = u0 > 0.f ? u0 : 0.2f * u0;
            u1 = u1 > 0.f ? u1 : 0.2f * u1;
            float mv = fmaxf(u0, u1);
            float e0 = expf(u0 - mv);
            float e1 = expf(u1 - mv);
            float Z = fc0s * e0 + fc1s * e1;
            wA = e0 / Z;
            wB = e1 / Z;
        } else {
            float inv = 1.f / dtot[b];
            wA = inv;
            wB = inv;
        }
        g_w[0][b][i] = wA;
        g_w[1][b][i] = wB;
    }
}

// ---------------------------------------------------------------------------
// Kernel 3.5: g_Hv[1] = bf16(e*H). 8 floats per thread (2 float4, same row j).
// ---------------------------------------------------------------------------
__global__ __launch_bounds__(256) void k_conv() {
    int idx = blockIdx.x * 256 + threadIdx.x;
    int base = idx * 8;                      // 8 floats, within one row j
    float4 h0 = *(const float4*)&g_H[base];
    float4 h1 = *(const float4*)&g_H[base + 4];
    float e = g_e[base >> 6];                // (b*NN + j)
    uint4 o;
    o.x = pack2bf(h0.x * e, h0.y * e);
    o.y = pack2bf(h0.z * e, h0.w * e);
    o.z = pack2bf(h1.x * e, h1.y * e);
    o.w = pack2bf(h1.z * e, h1.w * e);
    *(uint4*)&g_Hv[1][base] = o;
}

// ---------------------------------------------------------------------------
// Kernel 4: tensor-core fused attention GEMM, double-buffered smem.
// out[b,i,:] = tanh( wA*Sum_{j<1024} adj*Bv + wB*Sum_{j>=1024} adj*Bv + bias ) + H
// Block: 128 rows x 64 cols, 8 warps (4m x 2n), warp 32x32, K-tile 64.
// One __syncthreads per K-tile; store of tile k+1 overlaps MMA of tile k.
// ---------------------------------------------------------------------------
__device__ __forceinline__ unsigned exp2b(unsigned v) {
    return (v & 1u) * 0x3F80u | ((v >> 8) & 1u) * 0x3F800000u;
}

__device__ __forceinline__ void st_expand(uint4 v, __nv_bfloat16* dst) {
    uint4 d0 = make_uint4(exp2b(v.x & 0xFFFFu), exp2b(v.x >> 16),
                          exp2b(v.y & 0xFFFFu), exp2b(v.y >> 16));
    uint4 d1 = make_uint4(exp2b(v.z & 0xFFFFu), exp2b(v.z >> 16),
                          exp2b(v.w & 0xFFFFu), exp2b(v.w >> 16));
    ((uint4*)dst)[0] = d0;
    ((uint4*)dst)[1] = d1;
}

#define LDSM4(R, ADDR)                                                         \
    asm volatile("ldmatrix.sync.aligned.m8n8.x4.shared.b16 {%0,%1,%2,%3}, [%4];" \
                 : "=r"(R[0]), "=r"(R[1]), "=r"(R[2]), "=r"(R[3]) : "r"(ADDR))

#define LDSM4T(R, ADDR)                                                        \
    asm volatile("ldmatrix.sync.aligned.m8n8.x4.trans.shared.b16 {%0,%1,%2,%3}, [%4];" \
                 : "=r"(R[0]), "=r"(R[1]), "=r"(R[2]), "=r"(R[3]) : "r"(ADDR))

#define MMA16816(C, AR, B0, B1)                                                \
    asm volatile(                                                              \
        "mma.sync.aligned.m16n8k16.row.col.f32.bf16.bf16.f32 "                 \
        "{%0,%1,%2,%3}, {%4,%5,%6,%7}, {%8,%9}, {%0,%1,%2,%3};"                \
        : "+f"(C[0]), "+f"(C[1]), "+f"(C[2]), "+f"(C[3])                       \
        : "r"(AR[0]), "r"(AR[1]), "r"(AR[2]), "r"(AR[3]), "r"(B0), "r"(B1))

#define TILE_BODY(ACC)                                                         \
    {                                                                          \
        unsigned aSel = (kt & 1) ? A_BUF_BYTES : 0;                            \
        unsigned bSel = (kt & 1) ? B_BUF_BYTES : 0;                            \
        /* prefetch tile kt+1 from global */                                   \
        if (kt + 1 < 32) {                                                     \
            const unsigned char* ap = aGbase + (kt + 1) * 64;                  \
            pa0 = *(const uint4*)ap;                                           \
            pa1 = *(const uint4*)(ap + 16);                                    \
            const uint4* bp = (const uint4*)(HvB + ((kt + 1) * 64 + br) * DD); \
            pb0 = bp[bi1];                                                     \
            pb1 = bp[bi2];                                                     \
        }                                                                      \
        /* MMAs on buffer (kt&1) */                                            \
        _Pragma("unroll")                                                      \
        for (int k16 = 0; k16 < 4; k16++) {                                    \
            unsigned a0[4], a1[4], f0[4], f1[4];                               \
            LDSM4(a0, aA0 + aSel + k16 * 32);                                  \
            LDSM4(a1, aA1 + aSel + k16 * 32);                                  \
            LDSM4T(f0, aB0 + bSel + k16 * 16 * BSTR * 2);                      \
            LDSM4T(f1, aB1 + bSel + k16 * 16 * BSTR * 2);                      \
            MMA16816(ACC[0][0], a0, f0[0], f0[1]);                             \
            MMA16816(ACC[0][1], a0, f0[2], f0[3]);                             \
            MMA16816(ACC[0][2], a0, f1[0], f1[1]);                             \
            MMA16816(ACC[0][3], a0, f1[2], f1[3]);                             \
            MMA16816(ACC[1][0], a1, f0[0], f0[1]);                             \
            MMA16816(ACC[1][1], a1, f0[2], f0[3]);                             \
            MMA16816(ACC[1][2], a1, f1[0], f1[1]);                             \
            MMA16816(ACC[1][3], a1, f1[2], f1[3]);                             \
        }                                                                      \
        /* store tile kt+1 into the other buffer */                            \
        if (kt + 1 < 32) {                                                     \
            __nv_bfloat16* Ad = (__nv_bfloat16*)(dsm + (aSel ^ A_BUF_BYTES));  \
            __nv_bfloat16* Bd = (__nv_bfloat16*)(dsm + B_BASE_OFF + (bSel ^ B_BUF_BYTES)); \
            st_expand(pa0, &Ad[arA]);                                          \
            st_expand(pa1, &Ad[arA + 16]);                                     \
            *(uint4*)&Bd[brB] = pb0;                                           \
            *(uint4*)&Bd[brB + 32] = pb1;                                      \
        }                                                                      \
        __syncthreads();                                                       \
    }

__global__ __launch_bounds__(256) void k_main(const float* __restrict__ bias,
                                              float* __restrict__ out) {
    extern __shared__ __align__(16) char dsm[];
    __shared__ float wAs[128], wBs[128];

    int tid = threadIdx.x;
    int lane = tid & 31, warp = tid >> 5;
    int wm = warp & 3, wn = warp >> 2;
    int b = blockIdx.y;
    int i0 = blockIdx.x * 128;
    bool upper = (i0 >= NH);

    if (tid < 128) {
        wAs[tid] = g_w[0][b][i0 + tid];
        wBs[tid] = g_w[1][b][i0 + tid];
    }

    const __nv_bfloat16* HvB = g_Hv[upper ? 1 : 0] + (size_t)b * NN * DD;

    // A staging: 128 rows x 64 bytes; thread -> (row, 32-byte half)
    int ar = tid >> 1;
    int ak = (tid & 1) * 32;
    int arA = ar * ASTR + ak;
    const unsigned char* aGbase = g_adj8 + (size_t)(i0 + ar) * NN + ak;

    // B staging: 64 rows x 128 bytes; thread -> (row, two uint4 slots)
    int br = tid >> 2;
    int bi1 = tid & 3, bi2 = bi1 + 4;
    int brB = br * BSTR + bi1 * 8;

    unsigned asb = (unsigned)__cvta_generic_to_shared(dsm);
    unsigned bsb = asb + B_BASE_OFF;
    unsigned aA0 = asb + (unsigned)(((wm * 32 + (lane & 15)) * ASTR + (lane >> 4) * 8) * 2);
    unsigned aA1 = aA0 + 16 * ASTR * 2;
    unsigned aB0 = bsb + (unsigned)(((lane & 15) * BSTR + wn * 32 + (lane >> 4) * 8) * 2);
    unsigned aB1 = aB0 + 32;

    // preload tile 0 and stage into buffer 0
    uint4 pa0 = *(const uint4*)aGbase;
    uint4 pa1 = *(const uint4*)(aGbase + 16);
    const uint4* bp0 = (const uint4*)(HvB + br * DD);
    uint4 pb0 = bp0[bi1], pb1 = bp0[bi2];
    {
        __nv_bfloat16* Ad = (__nv_bfloat16*)dsm;
        __nv_bfloat16* Bd = (__nv_bfloat16*)(dsm + B_BASE_OFF);
        st_expand(pa0, &Ad[arA]);
        st_expand(pa1, &Ad[arA + 16]);
        *(uint4*)&Bd[brB] = pb0;
        *(uint4*)&Bd[brB + 32] = pb1;
    }
    __syncthreads();

    float accLo[2][4][4] = {};
    float accHi[2][4][4] = {};

    for (int kt = 0; kt < 16; kt++) TILE_BODY(accLo);
    for (int kt = 16; kt < 32; kt++) TILE_BODY(accHi);

    // epilogue: out = tanh(wA*accLo + wB*accHi + bias) + H
    int gID = lane >> 2, tig = lane & 3;
#pragma unroll
    for (int mt = 0; mt < 2; mt++) {
#pragma unroll
        for (int nt = 0; nt < 4; nt++) {
            int c = wn * 32 + nt * 8 + tig * 2;
            float bx = bias[c], by = bias[c + 1];
#pragma unroll
            for (int hseg = 0; hseg < 2; hseg++) {
                int r = wm * 32 + mt * 16 + gID + hseg * 8;
                float wa = wAs[r], wb = wBs[r];
                int ci = hseg * 2;
                float vx = wa * accLo[mt][nt][ci]     + wb * accHi[mt][nt][ci]     + bx;
                float vy = wa * accLo[mt][nt][ci + 1] + wb * accHi[mt][nt][ci + 1] + by;
                size_t o = ((size_t)b * NN + i0 + r) * DD + c;
                float2 h2 = *(const float2*)&g_H[o];
                float2 ov;
                ov.x = tanhf(vx) + h2.x;
                ov.y = tanhf(vy) + h2.y;
                *(float2*)&out[o] = ov;
            }
        }
    }
}

// ---------------------------------------------------------------------------
extern "C" void kernel_launch(void* const* d_in, const int* in_sizes, int n_in,
                              void* d_out, int out_size) {
    const float* x    = nullptr;
    const int*   adj  = nullptr;
    const float* Wm   = nullptr;
    const float* av   = nullptr;
    const float* bias = nullptr;
    for (int i = 0; i < n_in; i++) {
        switch (in_sizes[i]) {
            case BB * NN * CC: x    = (const float*)d_in[i]; break;
            case NN * NN:      adj  = (const int*)d_in[i];   break;
            case CC * DD:      Wm   = (const float*)d_in[i]; break;
            case 2 * DD:       av   = (const float*)d_in[i]; break;
            case DD:           bias = (const float*)d_in[i]; break;
            default: break;
        }
    }
    if (!x || !adj || !Wm || !av || !bias) return;
    float* out = (float*)d_out;

    cudaFuncSetAttribute(k_main, cudaFuncAttributeMaxDynamicSharedMemorySize,
                         DSMEM_BYTES);

    k_hidden<<<BB * NN / 64, 256>>>(x, Wm, av);
    k_prep<<<BB, 256>>>();
    k_aux<<<NN, 256>>>(adj);
    k_conv<<<(BB * NN * DD) / 2048, 256>>>();
    k_main<<<dim3(NN / 128, BB), 256, DSMEM_BYTES>>>(bias, out);
}